// round 1
// baseline (speedup 1.0000x reference)
#include <cuda_runtime.h>
#include <math.h>

// Problem constants
constexpr int B  = 2;
constexpr int L  = 2048;
constexpr int D  = 1024;
constexpr int H  = 16;
constexpr int DH = 64;
constexpr int BL = B * L;          // 4096 tokens
constexpr float EPS   = 1e-5f;
constexpr float SCALE = 0.125f;    // 1/sqrt(64)
constexpr float LOG_ROPE_BASE = 9.210340371976184f; // ln(10000)

// ---------------------------------------------------------------------------
// Scratch (static device memory; no runtime allocation)
// ---------------------------------------------------------------------------
__device__ float g_h[BL * D];            // post-LN hidden          16.8 MB
__device__ float g_qkv[BL * 3 * D];      // qkv projection          50.3 MB
__device__ float g_q[B * H * L * DH];    // q  [B,H,L,DH]           16.8 MB
__device__ float g_k[B * H * L * DH];    // k  [B,H,L,DH]
__device__ float g_v[B * H * L * DH];    // v  [B,H,L,DH]
__device__ float g_ctx[BL * D];          // attention output [B,L,H*DH]

// ---------------------------------------------------------------------------
// Block reduction (256 threads)
// ---------------------------------------------------------------------------
__device__ __forceinline__ float block_reduce_sum_256(float v, float* sbuf) {
    int tid = threadIdx.x;
    #pragma unroll
    for (int o = 16; o > 0; o >>= 1) v += __shfl_xor_sync(0xffffffffu, v, o);
    if ((tid & 31) == 0) sbuf[tid >> 5] = v;
    __syncthreads();
    if (tid < 8) {
        float w = sbuf[tid];
        #pragma unroll
        for (int o = 4; o > 0; o >>= 1) w += __shfl_xor_sync(0xffu, w, o);
        if (tid == 0) sbuf[0] = w;
    }
    __syncthreads();
    float r = sbuf[0];
    __syncthreads();
    return r;
}

// ---------------------------------------------------------------------------
// Kernel 1: LayerNorm over D=1024, one block (256 thr) per token.
// Each thread owns exactly one float4.
// ---------------------------------------------------------------------------
__global__ void __launch_bounds__(256) ln_kernel(
    const float* __restrict__ x,
    const float* __restrict__ w,
    const float* __restrict__ bias)
{
    __shared__ float sbuf[8];
    const int t   = blockIdx.x;
    const int tid = threadIdx.x;

    const float4 xv = *(const float4*)(x + (size_t)t * D + 4 * tid);
    float s  = xv.x + xv.y + xv.z + xv.w;
    float ss = fmaf(xv.x, xv.x, fmaf(xv.y, xv.y, fmaf(xv.z, xv.z, xv.w * xv.w)));
    s  = block_reduce_sum_256(s,  sbuf);
    ss = block_reduce_sum_256(ss, sbuf);

    const float mu = s * (1.0f / D);
    const float rs = rsqrtf(ss * (1.0f / D) - mu * mu + EPS);

    const float4 wv = *(const float4*)(w    + 4 * tid);
    const float4 bv = *(const float4*)(bias + 4 * tid);
    float4 ov;
    ov.x = (xv.x - mu) * rs * wv.x + bv.x;
    ov.y = (xv.y - mu) * rs * wv.y + bv.y;
    ov.z = (xv.z - mu) * rs * wv.z + bv.z;
    ov.w = (xv.w - mu) * rs * wv.w + bv.w;
    *(float4*)(g_h + (size_t)t * D + 4 * tid) = ov;
}

// ---------------------------------------------------------------------------
// Kernel 2/5: SGEMM-NT  C[m,n] = sum_k A[m,k] * Bm[n,k]
// A: [M,K] row-major, Bm: [N,K] row-major. 128x128x16 tile, 256 threads,
// each thread computes an 8x8 fragment.
// ---------------------------------------------------------------------------
constexpr int GBM = 128, GBN = 128, GBK = 16;

__global__ void __launch_bounds__(256) gemm_nt_kernel(
    const float* __restrict__ A,
    const float* __restrict__ Bm,
    float* __restrict__ C,
    int M, int N, int K)
{
    __shared__ float As[GBK][GBM];
    __shared__ float Bs[GBK][GBN];

    const int tid = threadIdx.x;
    const int tx  = tid & 15;
    const int ty  = tid >> 4;
    const int m0  = blockIdx.y * GBM;
    const int n0  = blockIdx.x * GBN;

    float acc[8][8];
    #pragma unroll
    for (int i = 0; i < 8; i++)
        #pragma unroll
        for (int j = 0; j < 8; j++) acc[i][j] = 0.0f;

    for (int k0 = 0; k0 < K; k0 += GBK) {
        // Load 128x16 of A and B (2048 floats each) as float4, store transposed.
        #pragma unroll
        for (int r = 0; r < 2; r++) {
            int idx  = tid + r * 256;           // 0..511 float4 slots
            int row  = idx >> 2;                // 0..127
            int colb = (idx & 3) * 4;           // 0,4,8,12
            float4 av = *(const float4*)(A  + (size_t)(m0 + row) * K + k0 + colb);
            float4 bv = *(const float4*)(Bm + (size_t)(n0 + row) * K + k0 + colb);
            As[colb + 0][row] = av.x; As[colb + 1][row] = av.y;
            As[colb + 2][row] = av.z; As[colb + 3][row] = av.w;
            Bs[colb + 0][row] = bv.x; Bs[colb + 1][row] = bv.y;
            Bs[colb + 2][row] = bv.z; Bs[colb + 3][row] = bv.w;
        }
        __syncthreads();

        #pragma unroll
        for (int kk = 0; kk < GBK; kk++) {
            float af[8], bf[8];
            *(float4*)&af[0] = *(const float4*)&As[kk][ty * 8];
            *(float4*)&af[4] = *(const float4*)&As[kk][ty * 8 + 4];
            *(float4*)&bf[0] = *(const float4*)&Bs[kk][tx * 8];
            *(float4*)&bf[4] = *(const float4*)&Bs[kk][tx * 8 + 4];
            #pragma unroll
            for (int i = 0; i < 8; i++)
                #pragma unroll
                for (int j = 0; j < 8; j++)
                    acc[i][j] = fmaf(af[i], bf[j], acc[i][j]);
        }
        __syncthreads();
    }

    #pragma unroll
    for (int i = 0; i < 8; i++) {
        float* cr = C + (size_t)(m0 + ty * 8 + i) * N + n0 + tx * 8;
        *(float4*)(cr)     = make_float4(acc[i][0], acc[i][1], acc[i][2], acc[i][3]);
        *(float4*)(cr + 4) = make_float4(acc[i][4], acc[i][5], acc[i][6], acc[i][7]);
    }
}

// ---------------------------------------------------------------------------
// Kernel 3: per-token weight-only LN on q and k segments + RoPE + transpose
// into [B,H,L,DH]; v is transposed only. One block (256 thr) per token.
// ---------------------------------------------------------------------------
__global__ void __launch_bounds__(256) qk_rope_kernel(
    const float* __restrict__ q_ln_w,
    const float* __restrict__ k_ln_w)
{
    __shared__ float sm[D];
    __shared__ float sbuf[8];

    const int t   = blockIdx.x;
    const int tid = threadIdx.x;
    const int b   = t / L;
    const int l   = t % L;

    #pragma unroll
    for (int seg = 0; seg < 2; seg++) {
        const float* base = g_qkv + (size_t)t * (3 * D) + seg * D;
        const float* w    = (seg == 0) ? q_ln_w : k_ln_w;
        float*       dst  = (seg == 0) ? g_q    : g_k;

        const float4 xv = *(const float4*)(base + 4 * tid);
        float s  = xv.x + xv.y + xv.z + xv.w;
        float ss = fmaf(xv.x, xv.x, fmaf(xv.y, xv.y, fmaf(xv.z, xv.z, xv.w * xv.w)));
        s  = block_reduce_sum_256(s,  sbuf);
        ss = block_reduce_sum_256(ss, sbuf);
        const float mu = s * (1.0f / D);
        const float rs = rsqrtf(ss * (1.0f / D) - mu * mu + EPS);

        const float4 wv = *(const float4*)(w + 4 * tid);
        sm[4 * tid + 0] = (xv.x - mu) * rs * wv.x;
        sm[4 * tid + 1] = (xv.y - mu) * rs * wv.y;
        sm[4 * tid + 2] = (xv.z - mu) * rs * wv.z;
        sm[4 * tid + 3] = (xv.w - mu) * rs * wv.w;
        __syncthreads();

        // RoPE: each thread produces 4 contiguous outputs (same head, same half)
        float out[4];
        #pragma unroll
        for (int c = 0; c < 4; c++) {
            int d  = 4 * tid + c;
            int dh = d & 63;
            int i  = dh & 31;
            float inv_freq = expf(-(float)(2 * i) * (1.0f / 64.0f) * LOG_ROPE_BASE);
            float freq = (float)l * inv_freq;
            float sn, cs;
            sincosf(freq, &sn, &cs);
            if (dh < 32) out[c] = sm[d] * cs - sm[d + 32] * sn;
            else         out[c] = sm[d] * cs + sm[d - 32] * sn;
        }
        const int d0   = 4 * tid;
        const int head = d0 >> 6;
        const int dh0  = d0 & 63;
        *(float4*)(dst + ((size_t)(b * H + head) * L + l) * DH + dh0) =
            make_float4(out[0], out[1], out[2], out[3]);
        __syncthreads();
    }

    // v: pure transpose
    {
        const float4 vv = *(const float4*)(g_qkv + (size_t)t * (3 * D) + 2 * D + 4 * tid);
        const int d0   = 4 * tid;
        const int head = d0 >> 6;
        const int dh0  = d0 & 63;
        *(float4*)(g_v + ((size_t)(b * H + head) * L + l) * DH + dh0) = vv;
    }
}

// ---------------------------------------------------------------------------
// Kernel 4: flash attention, fp32. grid = (L/64, B*H), 256 threads.
// Per block: 64 query rows, loop over 32 key tiles of 64.
// Dynamic smem layout:
//   Qt [64][68]  (Qt[d][i] = Q[i][d])
//   Kt [64][68]  (Kt[d][j] = K[j][d])
//   Vs [64][68]  (Vs[j][d])
//   Ps [64][68]  (Ps[j][i] = P[i][j])
//   m_s/l_s/al_s [64] each
// ---------------------------------------------------------------------------
constexpr int ATTN_PAD   = 68;
constexpr int ATTN_SMEM_FLOATS = 4 * 64 * ATTN_PAD + 3 * 64;
constexpr size_t ATTN_SMEM_BYTES = ATTN_SMEM_FLOATS * sizeof(float);

__global__ void __launch_bounds__(256) attn_kernel(float* __restrict__ ctx)
{
    extern __shared__ float smem[];
    float* Qt   = smem;
    float* Kt   = Qt + 64 * ATTN_PAD;
    float* Vs   = Kt + 64 * ATTN_PAD;
    float* Ps   = Vs + 64 * ATTN_PAD;
    float* m_s  = Ps + 64 * ATTN_PAD;
    float* l_s  = m_s + 64;
    float* al_s = l_s + 64;

    const int tid = threadIdx.x;
    const int tx  = tid & 15;
    const int ty  = tid >> 4;
    const int bh  = blockIdx.y;
    const int b   = bh / H;
    const int h   = bh % H;
    const int q0  = blockIdx.x * 64;

    const int i0 = ty * 4;   // query-row fragment base
    const int c0 = tx * 4;   // key-col / headdim fragment base

    // Load Q tile transposed
    const float* Qbase = g_q + ((size_t)bh * L + q0) * DH;
    #pragma unroll
    for (int r = 0; r < 4; r++) {
        int idx  = tid + r * 256;          // 1024 float4 slots
        int row  = idx >> 4;               // 0..63
        int colb = (idx & 15) * 4;         // 0..60
        float4 qv = *(const float4*)(Qbase + row * DH + colb);
        Qt[(colb + 0) * ATTN_PAD + row] = qv.x;
        Qt[(colb + 1) * ATTN_PAD + row] = qv.y;
        Qt[(colb + 2) * ATTN_PAD + row] = qv.z;
        Qt[(colb + 3) * ATTN_PAD + row] = qv.w;
    }
    if (tid < 64) { m_s[tid] = -1e30f; l_s[tid] = 0.0f; }

    float o[4][4];
    #pragma unroll
    for (int i = 0; i < 4; i++)
        #pragma unroll
        for (int j = 0; j < 4; j++) o[i][j] = 0.0f;

    __syncthreads();

    for (int kt = 0; kt < L / 64; kt++) {
        const float* Kbase = g_k + ((size_t)bh * L + kt * 64) * DH;
        const float* Vbase = g_v + ((size_t)bh * L + kt * 64) * DH;
        #pragma unroll
        for (int r = 0; r < 4; r++) {
            int idx  = tid + r * 256;
            int row  = idx >> 4;
            int colb = (idx & 15) * 4;
            float4 kv = *(const float4*)(Kbase + row * DH + colb);
            Kt[(colb + 0) * ATTN_PAD + row] = kv.x;
            Kt[(colb + 1) * ATTN_PAD + row] = kv.y;
            Kt[(colb + 2) * ATTN_PAD + row] = kv.z;
            Kt[(colb + 3) * ATTN_PAD + row] = kv.w;
            *(float4*)&Vs[row * ATTN_PAD + colb] = *(const float4*)(Vbase + row * DH + colb);
        }
        __syncthreads();

        // S = scale * Q K^T  (thread: rows i0..i0+3, cols c0..c0+3)
        float s[4][4];
        #pragma unroll
        for (int i = 0; i < 4; i++)
            #pragma unroll
            for (int j = 0; j < 4; j++) s[i][j] = 0.0f;

        #pragma unroll 8
        for (int d = 0; d < DH; d++) {
            float4 qf = *(const float4*)&Qt[d * ATTN_PAD + i0];
            float4 kf = *(const float4*)&Kt[d * ATTN_PAD + c0];
            float qa[4] = {qf.x, qf.y, qf.z, qf.w};
            float ka[4] = {kf.x, kf.y, kf.z, kf.w};
            #pragma unroll
            for (int i = 0; i < 4; i++)
                #pragma unroll
                for (int j = 0; j < 4; j++)
                    s[i][j] = fmaf(qa[i], ka[j], s[i][j]);
        }
        #pragma unroll
        for (int i = 0; i < 4; i++)
            #pragma unroll
            for (int j = 0; j < 4; j++)
                Ps[(c0 + j) * ATTN_PAD + (i0 + i)] = s[i][j] * SCALE;
        __syncthreads();

        // Online softmax, one thread per query row
        if (tid < 64) {
            const int i = tid;
            float mo = m_s[i];
            float mx = mo;
            for (int j = 0; j < 64; j++) mx = fmaxf(mx, Ps[j * ATTN_PAD + i]);
            float al  = __expf(mo - mx);
            float sum = 0.0f;
            for (int j = 0; j < 64; j++) {
                float p = __expf(Ps[j * ATTN_PAD + i] - mx);
                Ps[j * ATTN_PAD + i] = p;
                sum += p;
            }
            m_s[i]  = mx;
            l_s[i]  = l_s[i] * al + sum;
            al_s[i] = al;
        }
        __syncthreads();

        // Rescale accumulators, then O += P @ V
        float alr[4];
        #pragma unroll
        for (int i = 0; i < 4; i++) alr[i] = al_s[i0 + i];
        #pragma unroll
        for (int i = 0; i < 4; i++)
            #pragma unroll
            for (int d = 0; d < 4; d++) o[i][d] *= alr[i];

        #pragma unroll 8
        for (int j = 0; j < 64; j++) {
            float4 pf = *(const float4*)&Ps[j * ATTN_PAD + i0];
            float4 vf = *(const float4*)&Vs[j * ATTN_PAD + c0];
            float pa[4] = {pf.x, pf.y, pf.z, pf.w};
            float va[4] = {vf.x, vf.y, vf.z, vf.w};
            #pragma unroll
            for (int i = 0; i < 4; i++)
                #pragma unroll
                for (int d = 0; d < 4; d++)
                    o[i][d] = fmaf(pa[i], va[d], o[i][d]);
        }
        __syncthreads();
    }

    // Epilogue: normalize and write ctx[b, l, h*64 + c]
    #pragma unroll
    for (int i = 0; i < 4; i++) {
        const float inv = 1.0f / l_s[i0 + i];
        const int   lq  = q0 + i0 + i;
        *(float4*)(ctx + ((size_t)(b * L + lq) * D) + h * DH + c0) =
            make_float4(o[i][0] * inv, o[i][1] * inv, o[i][2] * inv, o[i][3] * inv);
    }
}

// ---------------------------------------------------------------------------
// Launch
// ---------------------------------------------------------------------------
extern "C" void kernel_launch(void* const* d_in, const int* in_sizes, int n_in,
                              void* d_out, int out_size)
{
    const float* x      = (const float*)d_in[0];
    const float* ln_w   = (const float*)d_in[1];
    const float* ln_b   = (const float*)d_in[2];
    const float* w_qkv  = (const float*)d_in[3];
    const float* q_ln_w = (const float*)d_in[4];
    const float* k_ln_w = (const float*)d_in[5];
    const float* w_out  = (const float*)d_in[6];
    float* out = (float*)d_out;

    // Resolve scratch symbol addresses (no allocation, capture-safe)
    float *h, *qkv, *ctx;
    cudaGetSymbolAddress((void**)&h,   g_h);
    cudaGetSymbolAddress((void**)&qkv, g_qkv);
    cudaGetSymbolAddress((void**)&ctx, g_ctx);

    cudaFuncSetAttribute(attn_kernel, cudaFuncAttributeMaxDynamicSharedMemorySize,
                         (int)ATTN_SMEM_BYTES);

    // 1. LN(x) -> g_h
    ln_kernel<<<BL, 256>>>(x, ln_w, ln_b);

    // 2. qkv = h @ w_qkv^T   [4096, 3072]
    {
        dim3 grid(3 * D / GBN, BL / GBM);
        gemm_nt_kernel<<<grid, 256>>>(h, w_qkv, qkv, BL, 3 * D, D);
    }

    // 3. q/k LN + RoPE + transpose, v transpose
    qk_rope_kernel<<<BL, 256>>>(q_ln_w, k_ln_w);

    // 4. attention -> g_ctx  [B,L,H*DH]
    {
        dim3 grid(L / 64, B * H);
        attn_kernel<<<grid, 256, ATTN_SMEM_BYTES>>>(ctx);
    }

    // 5. out = ctx @ w_out^T  [4096, 1024]
    {
        dim3 grid(D / GBN, BL / GBM);
        gemm_nt_kernel<<<grid, 256>>>(ctx, w_out, out, BL, D, D);
    }
}